// round 15
// baseline (speedup 1.0000x reference)
#include <cuda_runtime.h>
#include <cstdint>

#define RADIUS 4
#define DD 9
#define NB 16
#define NC 256
#define NH 96
#define NW 96
#define HW (NH * NW)
#define TYR 2                 // output rows per CTA
#define PX 8                  // pixels per thread along x
#define NG (NW / PX)          // 12
#define CC 8                  // channels per chunk
#define NCHUNK (NC / CC)      // 32
#define NCOMPUTE (NG * DD * TYR)  // 216
#define BLOCK 256
#define TH (TYR + 2 * RADIUS)     // 10 halo rows
#define CHUNK_B (CC * HW * 4)     // global bytes per chunk per tensor

// t rows: 27 chunks of 16B (432 B); s rows: 24 chunks (384 B)
#define TROW_B 432
#define TCH_B  (TH * TROW_B)       // 4320
#define TREG_B (CC * TCH_B)        // 34560
#define SROW_B 384
#define SCH_B  (TYR * SROW_B)      // 768
#define SREG_B (CC * SCH_B)        // 6144
#define BUF_B  (TREG_B + SREG_B)   // 40704
#define SMEM_B (2 * BUF_B)         // 81408

// chunk permutation: XOR-swizzle inside full 8-blocks (j<24), identity above.
#define PSW(j) (((j) < 24) ? ((j) ^ (((j) >> 3) & 3)) : (j))

union F2U { float2 f; unsigned long long u; };

__device__ __forceinline__ float2 ffma2(float2 a, float2 b, float2 c) {
    F2U ua, ub, uc, ud;
    ua.f = a; ub.f = b; uc.f = c;
    asm("fma.rn.f32x2 %0, %1, %2, %3;"
        : "=l"(ud.u) : "l"(ua.u), "l"(ub.u), "l"(uc.u));
    return ud.f;
}

__device__ __forceinline__ void cp16(uint32_t dst_smem, const void* src) {
    asm volatile("cp.async.cg.shared.global [%0], [%1], 16;\n"
                 :: "r"(dst_smem), "l"(src));
}
__device__ __forceinline__ void cp_commit() {
    asm volatile("cp.async.commit_group;\n" ::: "memory");
}
__device__ __forceinline__ void cp_wait0() {
    asm volatile("cp.async.wait_group 0;\n" ::: "memory");
}

// Ownership staging: each thread's slot offsets precomputed once.
__device__ __forceinline__ void do_stage(
    uint32_t buf, const char* __restrict__ ftk, const char* __restrict__ fsk,
    bool t_valid, uint32_t t_dst0, uint32_t t_src0,
    bool s_stage, uint32_t s_dst0, uint32_t s_src0)
{
    if (t_valid) {
#pragma unroll
        for (int c = 0; c < CC; ++c)
            cp16(buf + t_dst0 + c * TCH_B, ftk + t_src0 + (size_t)c * (HW * 4));
    }
    if (s_stage) {
#pragma unroll
        for (int c = 0; c < CC; ++c)
            cp16(buf + s_dst0 + c * SCH_B, fsk + s_src0 + (size_t)c * (HW * 4));
    }
}

__global__ __launch_bounds__(BLOCK, 2)
void corr_kernel(const float* __restrict__ fs, const float* __restrict__ ft,
                 float* __restrict__ out)
{
    extern __shared__ char smem[];

    const int b   = blockIdx.y;
    const int y0  = blockIdx.x * TYR;
    const int tid = threadIdx.x;
    const int wid = tid >> 5;              // warp id (phase rotation)
    const int g   = tid % NG;
    const int dy  = (tid / NG) % DD;
    const int r   = (tid / (NG * DD)) & 1;
    const bool active = (tid < NCOMPUTE);

    const uint32_t smem_s = (uint32_t)__cvta_generic_to_shared(smem);

    // ---- staging ownership (computed once) ----
    bool t_valid = false;
    uint32_t t_dst0 = 0, t_src0 = 0;
    if (tid < TH * 24) {                   // 240 t-slots
        int ro = tid / 24, q = tid - ro * 24;
        int gr = y0 + ro - RADIUS;
        t_valid = ((unsigned)gr < NH);
        t_dst0 = (uint32_t)(ro * TROW_B + (PSW(q + 1) << 4));
        t_src0 = (uint32_t)((gr * NW + 4 * q) * 4);
    }
    const bool s_stage = (tid >= 208);     // 48 s-slots on threads 208..255
    uint32_t s_dst0 = 0, s_src0 = 0;
    if (s_stage) {
        int i = tid - 208;
        int ro = i / 24, q = i - ro * 24;
        s_dst0 = (uint32_t)(TREG_B + ro * SROW_B + (PSW(q) << 4));
        s_src0 = (uint32_t)(((y0 + ro) * NW + 4 * q) * 4);
    }

    // ---- hoisted swizzled read offsets ----
    uint32_t t_off[4], s_off[2];
#pragma unroll
    for (int q = 0; q < 4; ++q)
        t_off[q] = (uint32_t)((r + dy) * TROW_B + (PSW(2 * g + q) << 4));
#pragma unroll
    for (int q = 0; q < 2; ++q)
        s_off[q] = (uint32_t)(TREG_B + r * SROW_B + (PSW(2 * g + q) << 4));

    // zero smem once: halo padding stays zero for all chunks
    for (int i = tid; i < SMEM_B / 16; i += BLOCK)
        *(float4*)(smem + i * 16) = make_float4(0.f, 0.f, 0.f, 0.f);
    __syncthreads();

    // accumulators: 72 scalars
    float2 accE[4][5];                     // even dx=2m, pixel pairs (2pp,2pp+1)
    float2 accM[3][4];                     // odd dx=2m+1, pixel pairs (2j+1,2j+2)
    float  acc0[4], acc7[4];               // odd dx edges, pixels 0 and 7
#pragma unroll
    for (int pp = 0; pp < 4; ++pp)
#pragma unroll
        for (int m = 0; m < 5; ++m) accE[pp][m] = make_float2(0.f, 0.f);
#pragma unroll
    for (int j = 0; j < 3; ++j)
#pragma unroll
        for (int m = 0; m < 4; ++m) accM[j][m] = make_float2(0.f, 0.f);
#pragma unroll
    for (int m = 0; m < 4; ++m) { acc0[m] = 0.f; acc7[m] = 0.f; }

    const char* ft_k = (const char*)(ft + (size_t)b * NC * HW);
    const char* fs_k = (const char*)(fs + (size_t)b * NC * HW);

    // prologue: stage chunk 0 into buffer 0
    do_stage(smem_s, ft_k, fs_k, t_valid, t_dst0, t_src0, s_stage, s_dst0, s_src0);
    cp_commit();
    ft_k += CHUNK_B; fs_k += CHUNK_B;

    for (int k = 0; k < NCHUNK; ++k) {
        const uint32_t cur = (uint32_t)(k & 1);
        cp_wait0();            // chunk k landed (committed one compute-phase ago)
        __syncthreads();       // ...and all warps past compute(k-1)

        if (k + 1 < NCHUNK) {
            do_stage(smem_s + (cur ^ 1) * BUF_B, ft_k, fs_k,
                     t_valid, t_dst0, t_src0, s_stage, s_dst0, s_src0);
            cp_commit();
            ft_k += CHUNK_B; fs_k += CHUNK_B;
        }

        if (active) {
            const char* bb = smem + cur * BUF_B;
            // warp-phase rotation: warps start at different channels so the
            // LDS/FMA duty cycles of the SM's warps interleave instead of
            // convoying (accumulation over c is order-independent).
#pragma unroll
            for (int cc = 0; cc < CC; ++cc) {
                const int c = (cc + wid) & (CC - 1);
                const char* tb = bb + c * TCH_B;
                const char* sb = bb + c * SCH_B;

                float4 T0 = *(const float4*)(tb + t_off[0]);
                float4 T1 = *(const float4*)(tb + t_off[1]);
                float4 T2 = *(const float4*)(tb + t_off[2]);
                float4 T3 = *(const float4*)(tb + t_off[3]);
                float4 S0 = *(const float4*)(sb + s_off[0]);
                float4 S1 = *(const float4*)(sb + s_off[1]);

                float2 te[8] = { {T0.x,T0.y},{T0.z,T0.w},{T1.x,T1.y},{T1.z,T1.w},
                                 {T2.x,T2.y},{T2.z,T2.w},{T3.x,T3.y},{T3.z,T3.w} };
                float2 se[4] = { {S0.x,S0.y},{S0.z,S0.w},{S1.x,S1.y},{S1.z,S1.w} };
                float2 sh[3] = { {S0.y,S0.z}, {S0.w,S1.x}, {S1.y,S1.z} };

#pragma unroll
                for (int pp = 0; pp < 4; ++pp)
#pragma unroll
                    for (int m = 0; m < 5; ++m)
                        accE[pp][m] = ffma2(se[pp], te[pp + m], accE[pp][m]);
#pragma unroll
                for (int j = 0; j < 3; ++j)
#pragma unroll
                    for (int m = 0; m < 4; ++m)
                        accM[j][m] = ffma2(sh[j], te[j + m + 1], accM[j][m]);
#pragma unroll
                for (int m = 0; m < 4; ++m) {
                    acc0[m] = fmaf(se[0].x, te[m].y,     acc0[m]);
                    acc7[m] = fmaf(se[3].y, te[4 + m].x, acc7[m]);
                }
            }
        }
    }

    if (active) {
        const float scale = 1.0f / (float)NC;
        const int y  = y0 + r;
        const int x0 = g * PX;
        float* ob = out + (((size_t)b * (DD * DD) + dy * DD) * NH + y) * NW + x0;
#pragma unroll
        for (int m = 0; m < 5; ++m) {
            float4 o0, o1;
            o0.x = accE[0][m].x * scale;  o0.y = accE[0][m].y * scale;
            o0.z = accE[1][m].x * scale;  o0.w = accE[1][m].y * scale;
            o1.x = accE[2][m].x * scale;  o1.y = accE[2][m].y * scale;
            o1.z = accE[3][m].x * scale;  o1.w = accE[3][m].y * scale;
            float* op = ob + (size_t)(2 * m) * HW;
            *(float4*)(op)     = o0;
            *(float4*)(op + 4) = o1;
        }
#pragma unroll
        for (int m = 0; m < 4; ++m) {
            float4 o0, o1;
            o0.x = acc0[m]       * scale;
            o0.y = accM[0][m].x  * scale;  o0.z = accM[0][m].y * scale;
            o0.w = accM[1][m].x  * scale;
            o1.x = accM[1][m].y  * scale;  o1.y = accM[2][m].x * scale;
            o1.z = accM[2][m].y  * scale;  o1.w = acc7[m]      * scale;
            float* op = ob + (size_t)(2 * m + 1) * HW;
            *(float4*)(op)     = o0;
            *(float4*)(op + 4) = o1;
        }
    }
}

extern "C" void kernel_launch(void* const* d_in, const int* in_sizes, int n_in,
                              void* d_out, int out_size)
{
    const float* fs = (const float*)d_in[0];   // feat_s
    const float* ft = (const float*)d_in[1];   // feat_t
    float* out = (float*)d_out;

    cudaFuncSetAttribute(corr_kernel, cudaFuncAttributeMaxDynamicSharedMemorySize,
                         SMEM_B);

    dim3 grid(NH / TYR, NB);   // (48, 16)
    corr_kernel<<<grid, BLOCK, SMEM_B>>>(fs, ft, out);
}

// round 16
// speedup vs baseline: 1.0007x; 1.0007x over previous
#include <cuda_runtime.h>
#include <cstdint>

#define RADIUS 4
#define DD 9
#define NB 16
#define NC 256
#define NH 96
#define NW 96
#define HW (NH * NW)
#define TYR 2                 // output rows per CTA
#define PX 8                  // pixels per thread along x
#define NG (NW / PX)          // 12
#define CC 8                  // channels per chunk
#define NCHUNK (NC / CC)      // 32
#define NCOMPUTE (NG * DD * TYR)  // 216
#define BLOCK 256
#define TH (TYR + 2 * RADIUS)     // 10 halo rows
#define CHUNK_B (CC * HW * 4)     // global bytes per chunk per tensor

// t rows: 27 chunks of 16B (432 B); s rows: 24 chunks (384 B)
#define TROW_B 432
#define TCH_B  (TH * TROW_B)       // 4320
#define TREG_B (CC * TCH_B)        // 34560
#define SROW_B 384
#define SCH_B  (TYR * SROW_B)      // 768
#define SREG_B (CC * SCH_B)        // 6144
#define BUF_B  (TREG_B + SREG_B)   // 40704
#define SMEM_B (2 * BUF_B)         // 81408

// chunk permutation: XOR-swizzle inside full 8-blocks (j<24), identity above.
#define PSW(j) (((j) < 24) ? ((j) ^ (((j) >> 3) & 3)) : (j))

union F2U { float2 f; unsigned long long u; };

__device__ __forceinline__ float2 ffma2(float2 a, float2 b, float2 c) {
    F2U ua, ub, uc, ud;
    ua.f = a; ub.f = b; uc.f = c;
    asm("fma.rn.f32x2 %0, %1, %2, %3;"
        : "=l"(ud.u) : "l"(ua.u), "l"(ub.u), "l"(uc.u));
    return ud.f;
}

__device__ __forceinline__ void cp16(uint32_t dst_smem, const void* src) {
    asm volatile("cp.async.cg.shared.global [%0], [%1], 16;\n"
                 :: "r"(dst_smem), "l"(src));
}
__device__ __forceinline__ void cp_commit() {
    asm volatile("cp.async.commit_group;\n" ::: "memory");
}
__device__ __forceinline__ void cp_wait0() {
    asm volatile("cp.async.wait_group 0;\n" ::: "memory");
}

// Ownership staging: each thread's slot offsets precomputed once.
__device__ __forceinline__ void do_stage(
    uint32_t buf, const char* __restrict__ ftk, const char* __restrict__ fsk,
    bool t_valid, uint32_t t_dst0, uint32_t t_src0,
    bool s_stage, uint32_t s_dst0, uint32_t s_src0)
{
    if (t_valid) {
#pragma unroll
        for (int c = 0; c < CC; ++c)
            cp16(buf + t_dst0 + c * TCH_B, ftk + t_src0 + (size_t)c * (HW * 4));
    }
    if (s_stage) {
#pragma unroll
        for (int c = 0; c < CC; ++c)
            cp16(buf + s_dst0 + c * SCH_B, fsk + s_src0 + (size_t)c * (HW * 4));
    }
}

__global__ __launch_bounds__(BLOCK, 2)
void corr_kernel(const float* __restrict__ fs, const float* __restrict__ ft,
                 float* __restrict__ out)
{
    extern __shared__ char smem[];

    const int b   = blockIdx.y;
    const int y0  = blockIdx.x * TYR;
    const int tid = threadIdx.x;
    const int wid = tid >> 5;              // warp id (phase rotation)
    const int g   = tid % NG;
    const int dy  = (tid / NG) % DD;
    const int r   = (tid / (NG * DD)) & 1;
    const bool active = (tid < NCOMPUTE);

    const uint32_t smem_s = (uint32_t)__cvta_generic_to_shared(smem);

    // ---- staging ownership (computed once) ----
    bool t_valid = false;
    uint32_t t_dst0 = 0, t_src0 = 0;
    if (tid < TH * 24) {                   // 240 t-slots
        int ro = tid / 24, q = tid - ro * 24;
        int gr = y0 + ro - RADIUS;
        t_valid = ((unsigned)gr < NH);
        t_dst0 = (uint32_t)(ro * TROW_B + (PSW(q + 1) << 4));
        t_src0 = (uint32_t)((gr * NW + 4 * q) * 4);
    }
    const bool s_stage = (tid >= 208);     // 48 s-slots on threads 208..255
    uint32_t s_dst0 = 0, s_src0 = 0;
    if (s_stage) {
        int i = tid - 208;
        int ro = i / 24, q = i - ro * 24;
        s_dst0 = (uint32_t)(TREG_B + ro * SROW_B + (PSW(q) << 4));
        s_src0 = (uint32_t)(((y0 + ro) * NW + 4 * q) * 4);
    }

    // ---- hoisted swizzled read offsets ----
    uint32_t t_off[4], s_off[2];
#pragma unroll
    for (int q = 0; q < 4; ++q)
        t_off[q] = (uint32_t)((r + dy) * TROW_B + (PSW(2 * g + q) << 4));
#pragma unroll
    for (int q = 0; q < 2; ++q)
        s_off[q] = (uint32_t)(TREG_B + r * SROW_B + (PSW(2 * g + q) << 4));

    // zero smem once: halo padding stays zero for all chunks
    for (int i = tid; i < SMEM_B / 16; i += BLOCK)
        *(float4*)(smem + i * 16) = make_float4(0.f, 0.f, 0.f, 0.f);
    __syncthreads();

    // accumulators: 72 scalars
    float2 accE[4][5];                     // even dx=2m, pixel pairs (2pp,2pp+1)
    float2 accM[3][4];                     // odd dx=2m+1, pixel pairs (2j+1,2j+2)
    float  acc0[4], acc7[4];               // odd dx edges, pixels 0 and 7
#pragma unroll
    for (int pp = 0; pp < 4; ++pp)
#pragma unroll
        for (int m = 0; m < 5; ++m) accE[pp][m] = make_float2(0.f, 0.f);
#pragma unroll
    for (int j = 0; j < 3; ++j)
#pragma unroll
        for (int m = 0; m < 4; ++m) accM[j][m] = make_float2(0.f, 0.f);
#pragma unroll
    for (int m = 0; m < 4; ++m) { acc0[m] = 0.f; acc7[m] = 0.f; }

    const char* ft_k = (const char*)(ft + (size_t)b * NC * HW);
    const char* fs_k = (const char*)(fs + (size_t)b * NC * HW);

    // prologue: stage chunk 0 into buffer 0
    do_stage(smem_s, ft_k, fs_k, t_valid, t_dst0, t_src0, s_stage, s_dst0, s_src0);
    cp_commit();
    ft_k += CHUNK_B; fs_k += CHUNK_B;

    for (int k = 0; k < NCHUNK; ++k) {
        const uint32_t cur = (uint32_t)(k & 1);
        cp_wait0();            // chunk k landed (committed one compute-phase ago)
        __syncthreads();       // ...and all warps past compute(k-1)

        if (k + 1 < NCHUNK) {
            do_stage(smem_s + (cur ^ 1) * BUF_B, ft_k, fs_k,
                     t_valid, t_dst0, t_src0, s_stage, s_dst0, s_src0);
            cp_commit();
            ft_k += CHUNK_B; fs_k += CHUNK_B;
        }

        if (active) {
            const char* bb = smem + cur * BUF_B;
            // warp-phase rotation: warps start at different channels so the
            // LDS/FMA duty cycles of the SM's warps interleave instead of
            // convoying (accumulation over c is order-independent).
#pragma unroll
            for (int cc = 0; cc < CC; ++cc) {
                const int c = (cc + wid) & (CC - 1);
                const char* tb = bb + c * TCH_B;
                const char* sb = bb + c * SCH_B;

                float4 T0 = *(const float4*)(tb + t_off[0]);
                float4 T1 = *(const float4*)(tb + t_off[1]);
                float4 T2 = *(const float4*)(tb + t_off[2]);
                float4 T3 = *(const float4*)(tb + t_off[3]);
                float4 S0 = *(const float4*)(sb + s_off[0]);
                float4 S1 = *(const float4*)(sb + s_off[1]);

                float2 te[8] = { {T0.x,T0.y},{T0.z,T0.w},{T1.x,T1.y},{T1.z,T1.w},
                                 {T2.x,T2.y},{T2.z,T2.w},{T3.x,T3.y},{T3.z,T3.w} };
                float2 se[4] = { {S0.x,S0.y},{S0.z,S0.w},{S1.x,S1.y},{S1.z,S1.w} };
                float2 sh[3] = { {S0.y,S0.z}, {S0.w,S1.x}, {S1.y,S1.z} };

#pragma unroll
                for (int pp = 0; pp < 4; ++pp)
#pragma unroll
                    for (int m = 0; m < 5; ++m)
                        accE[pp][m] = ffma2(se[pp], te[pp + m], accE[pp][m]);
#pragma unroll
                for (int j = 0; j < 3; ++j)
#pragma unroll
                    for (int m = 0; m < 4; ++m)
                        accM[j][m] = ffma2(sh[j], te[j + m + 1], accM[j][m]);
#pragma unroll
                for (int m = 0; m < 4; ++m) {
                    acc0[m] = fmaf(se[0].x, te[m].y,     acc0[m]);
                    acc7[m] = fmaf(se[3].y, te[4 + m].x, acc7[m]);
                }
            }
        }
    }

    if (active) {
        const float scale = 1.0f / (float)NC;
        const int y  = y0 + r;
        const int x0 = g * PX;
        float* ob = out + (((size_t)b * (DD * DD) + dy * DD) * NH + y) * NW + x0;
#pragma unroll
        for (int m = 0; m < 5; ++m) {
            float4 o0, o1;
            o0.x = accE[0][m].x * scale;  o0.y = accE[0][m].y * scale;
            o0.z = accE[1][m].x * scale;  o0.w = accE[1][m].y * scale;
            o1.x = accE[2][m].x * scale;  o1.y = accE[2][m].y * scale;
            o1.z = accE[3][m].x * scale;  o1.w = accE[3][m].y * scale;
            float* op = ob + (size_t)(2 * m) * HW;
            *(float4*)(op)     = o0;
            *(float4*)(op + 4) = o1;
        }
#pragma unroll
        for (int m = 0; m < 4; ++m) {
            float4 o0, o1;
            o0.x = acc0[m]       * scale;
            o0.y = accM[0][m].x  * scale;  o0.z = accM[0][m].y * scale;
            o0.w = accM[1][m].x  * scale;
            o1.x = accM[1][m].y  * scale;  o1.y = accM[2][m].x * scale;
            o1.z = accM[2][m].y  * scale;  o1.w = acc7[m]      * scale;
            float* op = ob + (size_t)(2 * m + 1) * HW;
            *(float4*)(op)     = o0;
            *(float4*)(op + 4) = o1;
        }
    }
}

extern "C" void kernel_launch(void* const* d_in, const int* in_sizes, int n_in,
                              void* d_out, int out_size)
{
    const float* fs = (const float*)d_in[0];   // feat_s
    const float* ft = (const float*)d_in[1];   // feat_t
    float* out = (float*)d_out;

    cudaFuncSetAttribute(corr_kernel, cudaFuncAttributeMaxDynamicSharedMemorySize,
                         SMEM_B);

    dim3 grid(NH / TYR, NB);   // (48, 16)
    corr_kernel<<<grid, BLOCK, SMEM_B>>>(fs, ft, out);
}

// round 17
// speedup vs baseline: 1.0252x; 1.0245x over previous
#include <cuda_runtime.h>
#include <cstdint>

#define RADIUS 4
#define DD 9
#define NB 16
#define NC 256
#define NH 96
#define NW 96
#define HW (NH * NW)
#define TYR 2                 // output rows per CTA
#define PX 8                  // pixels per thread along x
#define NG (NW / PX)          // 12
#define CC 8                  // channels per chunk
#define NCHUNK (NC / CC)      // 32
#define NCOMPUTE (NG * DD * TYR)  // 216
#define BLOCK 256
#define TH (TYR + 2 * RADIUS)     // 10 halo rows
#define CHUNK_B (CC * HW * 4)     // global bytes per chunk per tensor

// t rows: 27 chunks of 16B (432 B); s rows: 24 chunks (384 B)
#define TROW_B 432
#define TCH_B  (TH * TROW_B)       // 4320
#define TREG_B (CC * TCH_B)        // 34560
#define SROW_B 384
#define SCH_B  (TYR * SROW_B)      // 768
#define SREG_B (CC * SCH_B)        // 6144
#define BUF_B  (TREG_B + SREG_B)   // 40704
#define SMEM_B (2 * BUF_B)         // 81408

// chunk permutation: XOR-swizzle inside full 8-blocks (j<24), identity above.
#define PSW(j) (((j) < 24) ? ((j) ^ (((j) >> 3) & 3)) : (j))

union F2U { float2 f; unsigned long long u; };

__device__ __forceinline__ float2 ffma2(float2 a, float2 b, float2 c) {
    F2U ua, ub, uc, ud;
    ua.f = a; ub.f = b; uc.f = c;
    asm("fma.rn.f32x2 %0, %1, %2, %3;"
        : "=l"(ud.u) : "l"(ua.u), "l"(ub.u), "l"(uc.u));
    return ud.f;
}

__device__ __forceinline__ void cp16(uint32_t dst_smem, const void* src) {
    asm volatile("cp.async.cg.shared.global [%0], [%1], 16;\n"
                 :: "r"(dst_smem), "l"(src));
}
__device__ __forceinline__ void cp_commit() {
    asm volatile("cp.async.commit_group;\n" ::: "memory");
}
__device__ __forceinline__ void cp_wait0() {
    asm volatile("cp.async.wait_group 0;\n" ::: "memory");
}

// Ownership staging: each thread's slot offsets precomputed once.
__device__ __forceinline__ void do_stage(
    uint32_t buf, const char* __restrict__ ftk, const char* __restrict__ fsk,
    bool t_valid, uint32_t t_dst0, uint32_t t_src0,
    bool s_stage, uint32_t s_dst0, uint32_t s_src0)
{
    if (t_valid) {
#pragma unroll
        for (int c = 0; c < CC; ++c)
            cp16(buf + t_dst0 + c * TCH_B, ftk + t_src0 + (size_t)c * (HW * 4));
    }
    if (s_stage) {
#pragma unroll
        for (int c = 0; c < CC; ++c)
            cp16(buf + s_dst0 + c * SCH_B, fsk + s_src0 + (size_t)c * (HW * 4));
    }
}

// One channel's 72 MACs from operand bank (T0..T3, S0, S1).
__device__ __forceinline__ void compute_ch(
    const float4& T0, const float4& T1, const float4& T2, const float4& T3,
    const float4& S0, const float4& S1,
    float2 (&accE)[4][5], float2 (&accM)[3][4],
    float (&acc0)[4], float (&acc7)[4])
{
    float2 te[8] = { {T0.x,T0.y},{T0.z,T0.w},{T1.x,T1.y},{T1.z,T1.w},
                     {T2.x,T2.y},{T2.z,T2.w},{T3.x,T3.y},{T3.z,T3.w} };
    float2 se[4] = { {S0.x,S0.y},{S0.z,S0.w},{S1.x,S1.y},{S1.z,S1.w} };
    float2 sh[3] = { {S0.y,S0.z}, {S0.w,S1.x}, {S1.y,S1.z} };

#pragma unroll
    for (int pp = 0; pp < 4; ++pp)
#pragma unroll
        for (int m = 0; m < 5; ++m)
            accE[pp][m] = ffma2(se[pp], te[pp + m], accE[pp][m]);
#pragma unroll
    for (int j = 0; j < 3; ++j)
#pragma unroll
        for (int m = 0; m < 4; ++m)
            accM[j][m] = ffma2(sh[j], te[j + m + 1], accM[j][m]);
#pragma unroll
    for (int m = 0; m < 4; ++m) {
        acc0[m] = fmaf(se[0].x, te[m].y,     acc0[m]);
        acc7[m] = fmaf(se[3].y, te[4 + m].x, acc7[m]);
    }
}

#define LOAD_BANK(Ta, Tb, Tc, Td, Sa, Sb, base, ch)                          \
    do {                                                                     \
        const char* tb_ = (base) + (ch) * TCH_B;                             \
        const char* sb_ = (base) + (ch) * SCH_B;                             \
        Ta = *(const float4*)(tb_ + t_off[0]);                               \
        Tb = *(const float4*)(tb_ + t_off[1]);                               \
        Tc = *(const float4*)(tb_ + t_off[2]);                               \
        Td = *(const float4*)(tb_ + t_off[3]);                               \
        Sa = *(const float4*)(sb_ + s_off[0]);                               \
        Sb = *(const float4*)(sb_ + s_off[1]);                               \
    } while (0)

__global__ __launch_bounds__(BLOCK, 2)
void corr_kernel(const float* __restrict__ fs, const float* __restrict__ ft,
                 float* __restrict__ out)
{
    extern __shared__ char smem[];

    const int b   = blockIdx.y;
    const int y0  = blockIdx.x * TYR;
    const int tid = threadIdx.x;
    const int g   = tid % NG;
    const int dy  = (tid / NG) % DD;
    const int r   = (tid / (NG * DD)) & 1;
    const bool active = (tid < NCOMPUTE);

    const uint32_t smem_s = (uint32_t)__cvta_generic_to_shared(smem);

    // ---- staging ownership (computed once) ----
    bool t_valid = false;
    uint32_t t_dst0 = 0, t_src0 = 0;
    if (tid < TH * 24) {                   // 240 t-slots
        int ro = tid / 24, q = tid - ro * 24;
        int gr = y0 + ro - RADIUS;
        t_valid = ((unsigned)gr < NH);
        t_dst0 = (uint32_t)(ro * TROW_B + (PSW(q + 1) << 4));
        t_src0 = (uint32_t)((gr * NW + 4 * q) * 4);
    }
    const bool s_stage = (tid >= 208);     // 48 s-slots on threads 208..255
    uint32_t s_dst0 = 0, s_src0 = 0;
    if (s_stage) {
        int i = tid - 208;
        int ro = i / 24, q = i - ro * 24;
        s_dst0 = (uint32_t)(TREG_B + ro * SROW_B + (PSW(q) << 4));
        s_src0 = (uint32_t)(((y0 + ro) * NW + 4 * q) * 4);
    }

    // ---- hoisted swizzled read offsets ----
    uint32_t t_off[4], s_off[2];
#pragma unroll
    for (int q = 0; q < 4; ++q)
        t_off[q] = (uint32_t)((r + dy) * TROW_B + (PSW(2 * g + q) << 4));
#pragma unroll
    for (int q = 0; q < 2; ++q)
        s_off[q] = (uint32_t)(TREG_B + r * SROW_B + (PSW(2 * g + q) << 4));

    // zero smem once: halo padding stays zero for all chunks
    for (int i = tid; i < SMEM_B / 16; i += BLOCK)
        *(float4*)(smem + i * 16) = make_float4(0.f, 0.f, 0.f, 0.f);
    __syncthreads();

    // accumulators: 72 scalars
    float2 accE[4][5];
    float2 accM[3][4];
    float  acc0[4], acc7[4];
#pragma unroll
    for (int pp = 0; pp < 4; ++pp)
#pragma unroll
        for (int m = 0; m < 5; ++m) accE[pp][m] = make_float2(0.f, 0.f);
#pragma unroll
    for (int j = 0; j < 3; ++j)
#pragma unroll
        for (int m = 0; m < 4; ++m) accM[j][m] = make_float2(0.f, 0.f);
#pragma unroll
    for (int m = 0; m < 4; ++m) { acc0[m] = 0.f; acc7[m] = 0.f; }

    const char* ft_k = (const char*)(ft + (size_t)b * NC * HW);
    const char* fs_k = (const char*)(fs + (size_t)b * NC * HW);

    // prologue: stage chunk 0 into buffer 0
    do_stage(smem_s, ft_k, fs_k, t_valid, t_dst0, t_src0, s_stage, s_dst0, s_src0);
    cp_commit();
    ft_k += CHUNK_B; fs_k += CHUNK_B;

    for (int k = 0; k < NCHUNK; ++k) {
        const uint32_t cur = (uint32_t)(k & 1);
        cp_wait0();            // chunk k landed (committed one compute-phase ago)
        __syncthreads();       // ...and all warps past compute(k-1)

        if (k + 1 < NCHUNK) {
            do_stage(smem_s + (cur ^ 1) * BUF_B, ft_k, fs_k,
                     t_valid, t_dst0, t_src0, s_stage, s_dst0, s_src0);
            cp_commit();
            ft_k += CHUNK_B; fs_k += CHUNK_B;
        }

        if (active) {
            const char* bb = smem + cur * BUF_B;
            // explicit 2-deep channel pipeline: bank B loads while bank A
            // computes, and vice versa — LDS latency hidden inside the warp.
            float4 Ta0, Ta1, Ta2, Ta3, Sa0, Sa1;
            float4 Tb0, Tb1, Tb2, Tb3, Sb0, Sb1;
            LOAD_BANK(Ta0, Ta1, Ta2, Ta3, Sa0, Sa1, bb, 0);
#pragma unroll
            for (int c = 0; c < CC; c += 2) {
                LOAD_BANK(Tb0, Tb1, Tb2, Tb3, Sb0, Sb1, bb, c + 1);
                compute_ch(Ta0, Ta1, Ta2, Ta3, Sa0, Sa1, accE, accM, acc0, acc7);
                if (c + 2 < CC)
                    LOAD_BANK(Ta0, Ta1, Ta2, Ta3, Sa0, Sa1, bb, c + 2);
                compute_ch(Tb0, Tb1, Tb2, Tb3, Sb0, Sb1, accE, accM, acc0, acc7);
            }
        }
    }

    if (active) {
        const float scale = 1.0f / (float)NC;
        const int y  = y0 + r;
        const int x0 = g * PX;
        float* ob = out + (((size_t)b * (DD * DD) + dy * DD) * NH + y) * NW + x0;
#pragma unroll
        for (int m = 0; m < 5; ++m) {
            float4 o0, o1;
            o0.x = accE[0][m].x * scale;  o0.y = accE[0][m].y * scale;
            o0.z = accE[1][m].x * scale;  o0.w = accE[1][m].y * scale;
            o1.x = accE[2][m].x * scale;  o1.y = accE[2][m].y * scale;
            o1.z = accE[3][m].x * scale;  o1.w = accE[3][m].y * scale;
            float* op = ob + (size_t)(2 * m) * HW;
            *(float4*)(op)     = o0;
            *(float4*)(op + 4) = o1;
        }
#pragma unroll
        for (int m = 0; m < 4; ++m) {
            float4 o0, o1;
            o0.x = acc0[m]       * scale;
            o0.y = accM[0][m].x  * scale;  o0.z = accM[0][m].y * scale;
            o0.w = accM[1][m].x  * scale;
            o1.x = accM[1][m].y  * scale;  o1.y = accM[2][m].x * scale;
            o1.z = accM[2][m].y  * scale;  o1.w = acc7[m]      * scale;
            float* op = ob + (size_t)(2 * m + 1) * HW;
            *(float4*)(op)     = o0;
            *(float4*)(op + 4) = o1;
        }
    }
}

extern "C" void kernel_launch(void* const* d_in, const int* in_sizes, int n_in,
                              void* d_out, int out_size)
{
    const float* fs = (const float*)d_in[0];   // feat_s
    const float* ft = (const float*)d_in[1];   // feat_t
    float* out = (float*)d_out;

    cudaFuncSetAttribute(corr_kernel, cudaFuncAttributeMaxDynamicSharedMemorySize,
                         SMEM_B);

    dim3 grid(NH / TYR, NB);   // (48, 16)
    corr_kernel<<<grid, BLOCK, SMEM_B>>>(fs, ft, out);
}